// round 4
// baseline (speedup 1.0000x reference)
#include <cuda_runtime.h>
#include <cstdint>
#include <cstddef>

// ---------------------------------------------------------------- constants
#define NB   4
#define NS_N 10000
#define NT_N 10000
#define NE   160000
#define NK   16
#define ND   128
#define M_NODES (NB * NS_N)            // 40000
#define TILES_NODE 313                 // ceil(40000/128)
#define TILES_EDGE (NB * NE / 128)     // 5000
#define TILES_PER_BATCH (NE / 128)     // 1250

// SMEM (floats): A[128][132], B[128][136], C[128][132]
#define LDA 132
#define LDB 136
#define LDC 132
#define OFF_B (128 * LDA)              // 16896
#define OFF_C (OFF_B + 128 * LDB)      // 34304
#define SMEM_FLOATS (OFF_C + 128 * LDC)
#define SMEM_BYTES (SMEM_FLOATS * 4)   // 204800

#define GRID_P 148

// ---------------------------------------------------------------- scratch
__device__ float g_Ps[(size_t)NB * NS_N * ND];
__device__ float g_Pt[(size_t)NB * NT_N * ND];
__device__ float g_dbond[(size_t)NB * NE * ND];
__device__ float g_bred[(size_t)NB * NT_N * ND];
__device__ float g_tmp[(size_t)NB * NT_N * ND];   // bred @ We2t

// ---------------------------------------------------------------- helpers
__device__ __forceinline__ unsigned f2tf(float f) {
    unsigned r; asm("cvt.rna.tf32.f32 %0, %1;" : "=r"(r) : "f"(f)); return r;
}
__device__ __forceinline__ void mma8(float c[4], const unsigned a[4], const unsigned b[2]) {
    asm volatile(
        "mma.sync.aligned.m16n8k8.row.col.f32.tf32.tf32.f32 "
        "{%0,%1,%2,%3},{%4,%5,%6,%7},{%8,%9},{%0,%1,%2,%3};"
        : "+f"(c[0]), "+f"(c[1]), "+f"(c[2]), "+f"(c[3])
        : "r"(a[0]), "r"(a[1]), "r"(a[2]), "r"(a[3]), "r"(b[0]), "r"(b[1]));
}
__device__ __forceinline__ float silu_f(float x) { return x / (1.f + __expf(-x)); }

// A tile stage: raw fp32 (exact values reusable in epilogue), rows clamped to M-1
__device__ __forceinline__ void stage_A(float* Ash, const float* __restrict__ A,
                                        size_t row0, size_t M, int tid) {
    #pragma unroll
    for (int i = 0; i < 16; ++i) {
        int t = tid + i * 256;
        int r = t >> 5, c4 = (t & 31) << 2;
        size_t rr = row0 + (size_t)r;
        if (rr >= M) rr = M - 1;
        *(float4*)(Ash + r * LDA + c4) = *(const float4*)(A + rr * ND + c4);
    }
}
// Weight stage: [k][n] row-major, tf32-rounded once
__device__ __forceinline__ void stage_W(float* Bsh, const float* __restrict__ W, int tid) {
    #pragma unroll
    for (int i = 0; i < 16; ++i) {
        int t = tid + i * 256;
        int r = t >> 5, c4 = (t & 31) << 2;
        float4 v = *(const float4*)(W + r * ND + c4);
        v.x = __uint_as_float(f2tf(v.x));
        v.y = __uint_as_float(f2tf(v.y));
        v.z = __uint_as_float(f2tf(v.z));
        v.w = __uint_as_float(f2tf(v.w));
        *(float4*)(Bsh + r * LDB + c4) = v;
    }
}

__device__ __forceinline__ void ldfragA(const float* Ash, int kk, int wm, int lr, int lc,
                                        unsigned a[16]) {
    int k0 = kk * 8;
    #pragma unroll
    for (int i = 0; i < 4; ++i) {
        int r = wm * 64 + i * 16 + lr;
        a[i * 4 + 0] = f2tf(Ash[r * LDA + k0 + lc]);
        a[i * 4 + 1] = f2tf(Ash[(r + 8) * LDA + k0 + lc]);
        a[i * 4 + 2] = f2tf(Ash[r * LDA + k0 + 4 + lc]);
        a[i * 4 + 3] = f2tf(Ash[(r + 8) * LDA + k0 + 4 + lc]);
    }
}
__device__ __forceinline__ void ldfragB(const float* Bsh, int kk, int wn, int lr, int lc,
                                        unsigned b[16]) {
    int k0 = kk * 8;
    #pragma unroll
    for (int j = 0; j < 8; ++j) {
        int n0 = wn * 64 + j * 8 + lr;
        b[j * 2 + 0] = __float_as_uint(Bsh[(k0 + lc) * LDB + n0]);
        b[j * 2 + 1] = __float_as_uint(Bsh[(k0 + 4 + lc) * LDB + n0]);
    }
}

// 128x128x128 tile GEMM, warps 0-3 in 2x2 grid (warp tile 64x64), pipelined k-loop
__device__ __forceinline__ void tile_gemm(const float* Ash, const float* Bsh,
                                          float c[4][8][4], int wm, int wn, int lane) {
    int lr = lane >> 2, lc = lane & 3;
    unsigned a0[16], a1[16], b0[16], b1[16];
    ldfragA(Ash, 0, wm, lr, lc, a0);
    ldfragB(Bsh, 0, wn, lr, lc, b0);
    #pragma unroll
    for (int kk = 0; kk < 16; ++kk) {
        unsigned* ac = (kk & 1) ? a1 : a0;
        unsigned* bc = (kk & 1) ? b1 : b0;
        unsigned* an = (kk & 1) ? a0 : a1;
        unsigned* bn = (kk & 1) ? b0 : b1;
        if (kk < 15) {
            ldfragA(Ash, kk + 1, wm, lr, lc, an);
            ldfragB(Bsh, kk + 1, wn, lr, lc, bn);
        }
        #pragma unroll
        for (int i = 0; i < 4; ++i)
            #pragma unroll
            for (int j = 0; j < 8; ++j)
                mma8(c[i][j], ac + i * 4, bc + j * 2);
    }
}

__device__ __forceinline__ void stage_C(float* Csh, float c[4][8][4], int wm, int wn, int lane) {
    int lr = lane >> 2, lc = lane & 3;
    #pragma unroll
    for (int i = 0; i < 4; ++i)
        #pragma unroll
        for (int j = 0; j < 8; ++j) {
            int r = wm * 64 + i * 16 + lr;
            int col = wn * 64 + j * 8 + (lc << 1);
            *(float2*)(Csh + r * LDC + col)       = make_float2(c[i][j][0], c[i][j][1]);
            *(float2*)(Csh + (r + 8) * LDC + col) = make_float2(c[i][j][2], c[i][j][3]);
        }
}

__device__ __forceinline__ void zero_acc(float c[4][8][4]) {
    #pragma unroll
    for (int i = 0; i < 4; ++i)
        #pragma unroll
        for (int j = 0; j < 8; ++j)
            #pragma unroll
            for (int q = 0; q < 4; ++q) c[i][j][q] = 0.f;
}

// ---------------------------------------------------------------- K1: O = A @ W (persistent)
__global__ __launch_bounds__(256) void proj2_kernel(const float* __restrict__ src,
                                                    const float* __restrict__ tgt,
                                                    const float* __restrict__ Ws,
                                                    const float* __restrict__ Wt) {
    extern __shared__ float sm[];
    float* Ash = sm;
    float* Bsh = sm + OFF_B;
    float* Csh = sm + OFF_C;
    int tid = threadIdx.x, lane = tid & 31, wid = tid >> 5;
    int wm = wid & 1, wn = (wid >> 1) & 1;

    const float* A = blockIdx.y ? tgt : src;
    const float* W = blockIdx.y ? Wt : Ws;
    float* O = blockIdx.y ? g_Pt : g_Ps;

    stage_W(Bsh, W, tid);
    __syncthreads();

    for (int t = blockIdx.x; t < TILES_NODE; t += gridDim.x) {
        size_t row0 = (size_t)t * 128;
        stage_A(Ash, A, row0, (size_t)M_NODES, tid);
        __syncthreads();
        float c[4][8][4];
        zero_acc(c);
        if (wid < 4) {
            tile_gemm(Ash, Bsh, c, wm, wn, lane);
            stage_C(Csh, c, wm, wn, lane);
        }
        __syncthreads();
        int cc = lane << 2;
        #pragma unroll 1
        for (int r = wid * 16; r < wid * 16 + 16; ++r) {
            size_t gr = row0 + (size_t)r;
            if (gr < (size_t)M_NODES)
                *(float4*)(O + gr * ND + cc) = *(const float4*)(Csh + r * LDC + cc);
        }
        __syncthreads();
    }
}

// single-input variant: g_tmp = g_bred @ We2t
__global__ __launch_bounds__(256) void projA_kernel(const float* __restrict__ W) {
    extern __shared__ float sm[];
    float* Ash = sm;
    float* Bsh = sm + OFF_B;
    float* Csh = sm + OFF_C;
    int tid = threadIdx.x, lane = tid & 31, wid = tid >> 5;
    int wm = wid & 1, wn = (wid >> 1) & 1;

    stage_W(Bsh, W, tid);
    __syncthreads();

    for (int t = blockIdx.x; t < TILES_NODE; t += gridDim.x) {
        size_t row0 = (size_t)t * 128;
        stage_A(Ash, g_bred, row0, (size_t)M_NODES, tid);
        __syncthreads();
        float c[4][8][4];
        zero_acc(c);
        if (wid < 4) {
            tile_gemm(Ash, Bsh, c, wm, wn, lane);
            stage_C(Csh, c, wm, wn, lane);
        }
        __syncthreads();
        int cc = lane << 2;
        #pragma unroll 1
        for (int r = wid * 16; r < wid * 16 + 16; ++r) {
            size_t gr = row0 + (size_t)r;
            if (gr < (size_t)M_NODES)
                *(float4*)(g_tmp + gr * ND + cc) = *(const float4*)(Csh + r * LDC + cc);
        }
        __syncthreads();
    }
}

// ---------------------------------------------------------------- K2: edge block (persistent)
__global__ __launch_bounds__(256) void edge_kernel(const float* __restrict__ bond,
                                                   const float* __restrict__ We2e,
                                                   const float* __restrict__ lng,
                                                   const float* __restrict__ lnb,
                                                   const int* __restrict__ src_order,
                                                   const int* __restrict__ tgt_order,
                                                   float* __restrict__ out0) {
    extern __shared__ float sm[];
    float* Ash = sm;
    float* Bsh = sm + OFF_B;
    float* Csh = sm + OFF_C;
    int tid = threadIdx.x, lane = tid & 31, wid = tid >> 5;
    int wm = wid & 1, wn = (wid >> 1) & 1;
    int cc = lane << 2;

    stage_W(Bsh, We2e, tid);
    float4 gg = *(const float4*)(lng + cc);
    float4 bbv = *(const float4*)(lnb + cc);
    __syncthreads();

    for (int t = blockIdx.x; t < TILES_EDGE; t += gridDim.x) {
        size_t row0 = (size_t)t * 128;
        stage_A(Ash, bond, row0, (size_t)NB * NE, tid);
        __syncthreads();
        float c[4][8][4];
        zero_acc(c);
        if (wid < 4) {
            tile_gemm(Ash, Bsh, c, wm, wn, lane);
            stage_C(Csh, c, wm, wn, lane);
        }
        __syncthreads();

        int b = t / TILES_PER_BATCH;
        int el0 = (t - b * TILES_PER_BATCH) * 128;
        const float* PsB = g_Ps + (size_t)b * NS_N * ND;
        const float* PtB = g_Pt + (size_t)b * NT_N * ND;

        #pragma unroll 1
        for (int r = wid * 16; r < wid * 16 + 16; ++r) {
            int el = el0 + r;
            int si = __ldg(src_order + el);
            int ti = __ldg(tgt_order + el);
            float4 v  = *(const float4*)(Csh + r * LDC + cc);
            float4 ps = *(const float4*)(PsB + (size_t)si * ND + cc);
            float4 pt = *(const float4*)(PtB + (size_t)ti * ND + cc);
            float x0 = silu_f(v.x + ps.x + pt.x);
            float x1 = silu_f(v.y + ps.y + pt.y);
            float x2 = silu_f(v.z + ps.z + pt.z);
            float x3 = silu_f(v.w + ps.w + pt.w);
            float s = x0 + x1 + x2 + x3;
            float q = x0 * x0 + x1 * x1 + x2 * x2 + x3 * x3;
            #pragma unroll
            for (int o = 16; o > 0; o >>= 1) {
                s += __shfl_xor_sync(0xffffffffu, s, o);
                q += __shfl_xor_sync(0xffffffffu, q, o);
            }
            float mean = s * (1.f / ND);
            float var  = q * (1.f / ND) - mean * mean;
            float rstd = rsqrtf(var + 1e-5f);
            float y0 = (x0 - mean) * rstd * gg.x + bbv.x;
            float y1 = (x1 - mean) * rstd * gg.y + bbv.y;
            float y2 = (x2 - mean) * rstd * gg.z + bbv.z;
            float y3 = (x3 - mean) * rstd * gg.w + bbv.w;
            size_t off = (row0 + (size_t)r) * ND + cc;
            *(float4*)(g_dbond + off) = make_float4(y0, y1, y2, y3);
            float4 bd = *(const float4*)(Ash + r * LDA + cc);   // exact fp32 bond
            *(float4*)(out0 + off) = make_float4(bd.x + y0, bd.y + y1, bd.z + y2, bd.w + y3);
        }
        __syncthreads();
    }
}

// ---------------------------------------------------------------- K3: bond->node gather
__global__ __launch_bounds__(128) void gather_kernel(const int* __restrict__ edge_order,
                                                     const float* __restrict__ coef) {
    int bn = blockIdx.x;                 // 0 .. B*NT-1
    int b = bn / NT_N, nt = bn - b * NT_N;
    __shared__ int   eo[NK];
    __shared__ float cf[NK];
    if (threadIdx.x < NK) {
        eo[threadIdx.x] = edge_order[nt * NK + threadIdx.x];
        cf[threadIdx.x] = coef[nt * NK + threadIdx.x];
    }
    __syncthreads();
    int d = threadIdx.x;
    const float* base = g_dbond + (size_t)b * NE * ND;
    float acc = 0.f;
    #pragma unroll
    for (int k = 0; k < NK; ++k)
        acc += cf[k] * __ldg(base + (size_t)eo[k] * ND + d);
    g_bred[(size_t)bn * ND + d] = acc * (1.f / NK);
}

// ---------------------------------------------------------------- K5: out2 = tgt + LN(silu(tgt@Wt2t + g_tmp))
__global__ __launch_bounds__(256) void tgtfin_kernel(const float* __restrict__ tgt,
                                                     const float* __restrict__ Wt2t,
                                                     const float* __restrict__ lng,
                                                     const float* __restrict__ lnb,
                                                     float* __restrict__ out2) {
    extern __shared__ float sm[];
    float* Ash = sm;
    float* Bsh = sm + OFF_B;
    float* Csh = sm + OFF_C;
    int tid = threadIdx.x, lane = tid & 31, wid = tid >> 5;
    int wm = wid & 1, wn = (wid >> 1) & 1;
    int cc = lane << 2;

    stage_W(Bsh, Wt2t, tid);
    float4 gg = *(const float4*)(lng + cc);
    float4 bbv = *(const float4*)(lnb + cc);
    __syncthreads();

    for (int t = blockIdx.x; t < TILES_NODE; t += gridDim.x) {
        size_t row0 = (size_t)t * 128;
        stage_A(Ash, tgt, row0, (size_t)M_NODES, tid);
        __syncthreads();
        float c[4][8][4];
        zero_acc(c);
        if (wid < 4) {
            tile_gemm(Ash, Bsh, c, wm, wn, lane);
            stage_C(Csh, c, wm, wn, lane);
        }
        __syncthreads();

        #pragma unroll 1
        for (int r = wid * 16; r < wid * 16 + 16; ++r) {
            size_t gr = row0 + (size_t)r;
            if (gr >= (size_t)M_NODES) break;
            float4 v = *(const float4*)(Csh + r * LDC + cc);
            float4 tm = *(const float4*)(g_tmp + gr * ND + cc);
            float x0 = silu_f(v.x + tm.x);
            float x1 = silu_f(v.y + tm.y);
            float x2 = silu_f(v.z + tm.z);
            float x3 = silu_f(v.w + tm.w);
            float s = x0 + x1 + x2 + x3;
            float q = x0 * x0 + x1 * x1 + x2 * x2 + x3 * x3;
            #pragma unroll
            for (int o = 16; o > 0; o >>= 1) {
                s += __shfl_xor_sync(0xffffffffu, s, o);
                q += __shfl_xor_sync(0xffffffffu, q, o);
            }
            float mean = s * (1.f / ND);
            float var  = q * (1.f / ND) - mean * mean;
            float rstd = rsqrtf(var + 1e-5f);
            float y0 = (x0 - mean) * rstd * gg.x + bbv.x;
            float y1 = (x1 - mean) * rstd * gg.y + bbv.y;
            float y2 = (x2 - mean) * rstd * gg.z + bbv.z;
            float y3 = (x3 - mean) * rstd * gg.w + bbv.w;
            float4 tg = *(const float4*)(Ash + r * LDA + cc);   // exact fp32 tgt
            *(float4*)(out2 + gr * ND + cc) = make_float4(tg.x + y0, tg.y + y1, tg.z + y2, tg.w + y3);
        }
        __syncthreads();
    }
}

// ---------------------------------------------------------------- launch
extern "C" void kernel_launch(void* const* d_in, const int* in_sizes, int n_in,
                              void* d_out, int out_size) {
    const float* bond = (const float*)d_in[0];
    const float* src  = (const float*)d_in[1];
    const float* tgt  = (const float*)d_in[2];
    const float* Ws2e = (const float*)d_in[3];
    const float* Wt2e = (const float*)d_in[4];
    const float* We2e = (const float*)d_in[5];
    const float* ln1g = (const float*)d_in[6];
    const float* ln1b = (const float*)d_in[7];
    const float* We2t = (const float*)d_in[8];
    const float* Wt2t = (const float*)d_in[9];
    const float* ln2g = (const float*)d_in[10];
    const float* ln2b = (const float*)d_in[11];
    const float* coef = (const float*)d_in[12];
    const int* so = (const int*)d_in[13];
    const int* to = (const int*)d_in[14];
    const int* eo = (const int*)d_in[15];

    float* out0 = (float*)d_out;                     // [B,E,D]
    float* out1 = out0 + (size_t)NB * NE * ND;       // [B,NS,D]
    float* out2 = out1 + (size_t)NB * NS_N * ND;     // [B,NT,D]

    cudaFuncSetAttribute(proj2_kernel,  cudaFuncAttributeMaxDynamicSharedMemorySize, SMEM_BYTES);
    cudaFuncSetAttribute(projA_kernel,  cudaFuncAttributeMaxDynamicSharedMemorySize, SMEM_BYTES);
    cudaFuncSetAttribute(edge_kernel,   cudaFuncAttributeMaxDynamicSharedMemorySize, SMEM_BYTES);
    cudaFuncSetAttribute(tgtfin_kernel, cudaFuncAttributeMaxDynamicSharedMemorySize, SMEM_BYTES);

    // out1 = src
    cudaMemcpyAsync(out1, src, (size_t)NB * NS_N * ND * sizeof(float),
                    cudaMemcpyDeviceToDevice);

    proj2_kernel<<<dim3(GRID_P / 2, 2), 256, SMEM_BYTES>>>(src, tgt, Ws2e, Wt2e);
    edge_kernel<<<GRID_P, 256, SMEM_BYTES>>>(bond, We2e, ln1g, ln1b, so, to, out0);
    gather_kernel<<<NB * NT_N, 128>>>(eo, coef);
    projA_kernel<<<GRID_P, 256, SMEM_BYTES>>>(We2t);
    tgtfin_kernel<<<GRID_P, 256, SMEM_BYTES>>>(tgt, Wt2t, ln2g, ln2b, out2);
}